// round 15
// baseline (speedup 1.0000x reference)
#include <cuda_runtime.h>
#include <cuda_fp16.h>
#include <math.h>

// Problem constants
#define B_N   4096
#define M_N   256
#define D_N   256
#define TAU_F       0.2f
#define INV2TAU_F   2.5f
#define TOPO_F      0.5f
#define LEN_C_F     0.01f
#define SP_C_F      0.001f
#define NEIGH_LOG2  (-0.18033688011112042f)   // -log2(e)/8
#define NPAIR (B_N / 2)                       // 2048 row pairs
#define FULLM 0xffffffffu
#define WPAD  132                             // ws row pad (floats, 16B aligned)

// ---------------- device scratch ----------------
__device__ float g_dist[B_N * M_N];
__device__ float g_factor[M_N];
__device__ float g_wsq[M_N];
__device__ float g_rowp[M_N];
__device__ float g_pdpart[16];               // per-proto-block sum edge_prob * d2
__device__ float g_partial[NPAIR];
__device__ int   g_ctr;

// ---------------- helpers ----------------
__device__ __forceinline__ unsigned h2tanh(unsigned x) {
    unsigned y;
    asm("tanh.approx.f16x2 %0, %1;" : "=r"(y) : "r"(x));
    return y;
}
__device__ __forceinline__ unsigned h2sub(unsigned a, unsigned b) {
    unsigned r;
    asm("sub.f16x2 %0, %1, %2;" : "=r"(r) : "r"(a), "r"(b));
    return r;
}
__device__ __forceinline__ unsigned h2add(unsigned a, unsigned b) {
    unsigned r;
    asm("add.f16x2 %0, %1, %2;" : "=r"(r) : "r"(a), "r"(b));
    return r;
}
__device__ __forceinline__ void h2acc(unsigned h2, float& a, float& b) {
    __half2 h = *reinterpret_cast<__half2*>(&h2);
    float2 f = __half22float2(h);
    a += f.x; b += f.y;
}
__device__ __forceinline__ void h2accneg(unsigned h2, float& a, float& b) {
    __half2 h = *reinterpret_cast<__half2*>(&h2);
    float2 f = __half22float2(h);
    a -= f.x; b -= f.y;
}

// packed f32x2 FMA (sm_103a)
__device__ __forceinline__ unsigned long long ffma2(unsigned long long a,
                                                    unsigned long long b,
                                                    unsigned long long c) {
    unsigned long long d;
    asm("fma.rn.f32x2 %0, %1, %2, %3;" : "=l"(d) : "l"(a), "l"(b), "l"(c));
    return d;
}
__device__ __forceinline__ unsigned long long pack2(float x) {
    unsigned long long r;
    asm("mov.b64 %0, {%1, %1};" : "=l"(r) : "f"(x));
    return r;
}
__device__ __forceinline__ float2 unpack2(unsigned long long v) {
    float2 f;
    asm("mov.b64 {%0, %1}, %2;" : "=f"(f.x), "=f"(f.y) : "l"(v));
    return f;
}

__device__ __forceinline__ float block_reduce_256(float v, float* sh) {
    int t = threadIdx.x;
    sh[t] = v;
    __syncthreads();
    #pragma unroll
    for (int s = 128; s > 0; s >>= 1) {
        if (t < s) sh[t] += sh[t + s];
        __syncthreads();
    }
    float r = sh[0];
    __syncthreads();
    return r;
}

// ---------------- k_pre: rowp/factor (from E) + W row norms + ctr reset ----
__global__ __launch_bounds__(256) void k_pre(const float* __restrict__ E,
                                             const float* __restrict__ W) {
    __shared__ float red[256];
    const int i = blockIdx.x;
    const int j = threadIdx.x;

    if (i == 0 && j == 0) g_ctr = 0;

    float z = 0.5f * (E[i * M_N + j] + E[j * M_N + i]);
    float p = 0.0f;
    if (j != i) p = 1.0f / (1.0f + __expf(-z));
    float wv = W[i * M_N + j];

    float sp = block_reduce_256(p, red);
    float sw = block_reduce_256(wv * wv, red);

    if (j == 0) {
        g_rowp[i]   = sp;
        g_factor[i] = 1.0f + TOPO_F * sp / (float)(M_N - 1);
        g_wsq[i]    = sw;
    }
}

// ---------------- GEMM: 32 rows x 128 protos per block, 256 threads ------
// blocks 0..255: data distances; blocks 256..271: proto tiles -> pd partials.
// Thread tile 4 rows x 4 protos, packed f32x2 FMA, double-buffered W staging.
__global__ __launch_bounds__(256) void k_gemm(const float* __restrict__ A,
                                              const float* __restrict__ W,
                                              const float* __restrict__ E) {
    __shared__ __align__(16) float xs[32 * 256];        // 32 KB [row][k]
    __shared__ __align__(16) float ws[2][16 * WPAD];    // 16.9 KB [buf][kc][proto]
    __shared__ float s_wsq[128];
    __shared__ float s_xn[32];

    const int tid  = threadIdx.x;
    const int lane = tid & 31;
    const int w8   = tid >> 5;          // warp 0..7
    const int tx   = tid & 31;          // proto group: c0 + tx*4 .. +3
    const int ty   = tid >> 5;          // rows ty*4 .. ty*4+3
    const int bx   = blockIdx.x;
    const bool proto = (bx >= 256);
    const int pb   = proto ? bx - 256 : bx;
    const int r0   = (pb >> 1) * 32;
    const int c0   = (pb & 1) * 128;
    const float* Ain = proto ? W : A;

    // ---- block's proto norms ----
    if (tid < 128) s_wsq[tid] = g_wsq[c0 + tid];

    // ---- load A tile [32][256] (coalesced float4) ----
    #pragma unroll
    for (int it = 0; it < 8; ++it) {
        int fidx = it * 256 + tid;           // float4 index 0..2047
        int row = fidx >> 6, k4 = fidx & 63;
        float4 v = ((const float4*)(Ain + (r0 + row) * D_N))[k4];
        *(float4*)&xs[row * 256 + k4 * 4] = v;
    }
    __syncthreads();

    // ---- row norms: warp w8 -> rows w8*4 .. +3 ----
    #pragma unroll
    for (int rr = 0; rr < 4; ++rr) {
        int row = w8 * 4 + rr;
        const float4* xr4 = (const float4*)&xs[row * 256];
        float4 a = xr4[lane], b = xr4[lane + 32];
        float p = a.x*a.x + a.y*a.y + a.z*a.z + a.w*a.w
                + b.x*b.x + b.y*b.y + b.z*b.z + b.w*b.w;
        #pragma unroll
        for (int off = 16; off > 0; off >>= 1) p += __shfl_xor_sync(FULLM, p, off);
        if (lane == 0) s_xn[row] = p;
    }

    // ---- stage chunk 0: ws[0][dc][proto] for protos c0..c0+127 ----
    #pragma unroll
    for (int it = 0; it < 2; ++it) {
        int fidx = it * 256 + tid;           // 0..511
        int mm = fidx >> 2, dc4 = fidx & 3;
        float4 v = *(const float4*)&W[(c0 + mm) * 256 + dc4 * 4];
        ws[0][(dc4 * 4 + 0) * WPAD + mm] = v.x;
        ws[0][(dc4 * 4 + 1) * WPAD + mm] = v.y;
        ws[0][(dc4 * 4 + 2) * WPAD + mm] = v.z;
        ws[0][(dc4 * 4 + 3) * WPAD + mm] = v.w;
    }
    __syncthreads();

    unsigned long long acc[4][2];
    #pragma unroll
    for (int r = 0; r < 4; ++r) { acc[r][0] = 0ull; acc[r][1] = 0ull; }

    #pragma unroll 1
    for (int c = 0; c < 16; ++c) {
        const int b = c & 1;
        // prefetch next chunk into registers
        float4 pre[2];
        if (c < 15) {
            #pragma unroll
            for (int it = 0; it < 2; ++it) {
                int fidx = it * 256 + tid;
                int mm = fidx >> 2, dc4 = fidx & 3;
                pre[it] = *(const float4*)&W[(c0 + mm) * 256 + (c + 1) * 16 + dc4 * 4];
            }
        }

        // compute chunk c
        const float* wsb = ws[b];
        #pragma unroll
        for (int kq = 0; kq < 4; ++kq) {
            float4 xr[4];
            #pragma unroll
            for (int r = 0; r < 4; ++r)
                xr[r] = *(const float4*)&xs[(ty * 4 + r) * 256 + c * 16 + kq * 4];
            #pragma unroll
            for (int k2 = 0; k2 < 4; ++k2) {
                const int kc = kq * 4 + k2;
                ulonglong2 wv = *(const ulonglong2*)&wsb[kc * WPAD + tx * 4];
                #pragma unroll
                for (int r = 0; r < 4; ++r) {
                    float xv = (k2 == 0) ? xr[r].x : (k2 == 1) ? xr[r].y
                             : (k2 == 2) ? xr[r].z : xr[r].w;
                    unsigned long long xx = pack2(xv);
                    acc[r][0] = ffma2(xx, wv.x, acc[r][0]);
                    acc[r][1] = ffma2(xx, wv.y, acc[r][1]);
                }
            }
        }

        // stage next chunk into the other buffer
        if (c < 15) {
            float* wsn = ws[1 - b];
            #pragma unroll
            for (int it = 0; it < 2; ++it) {
                int fidx = it * 256 + tid;
                int mm = fidx >> 2, dc4 = fidx & 3;
                wsn[(dc4 * 4 + 0) * WPAD + mm] = pre[it].x;
                wsn[(dc4 * 4 + 1) * WPAD + mm] = pre[it].y;
                wsn[(dc4 * 4 + 2) * WPAD + mm] = pre[it].z;
                wsn[(dc4 * 4 + 3) * WPAD + mm] = pre[it].w;
            }
            __syncthreads();
        }
    }

    // ---- epilogue ----
    float wn0 = s_wsq[tx * 4 + 0], wn1 = s_wsq[tx * 4 + 1];
    float wn2 = s_wsq[tx * 4 + 2], wn3 = s_wsq[tx * 4 + 3];

    if (!proto) {
        #pragma unroll
        for (int r = 0; r < 4; ++r) {
            int row = r0 + ty * 4 + r;
            float xr = s_xn[ty * 4 + r];
            float2 a0 = unpack2(acc[r][0]), a1 = unpack2(acc[r][1]);
            float4 dv;
            dv.x = sqrtf(fmaxf(xr + wn0 - 2.0f * a0.x, 0.0f));
            dv.y = sqrtf(fmaxf(xr + wn1 - 2.0f * a0.y, 0.0f));
            dv.z = sqrtf(fmaxf(xr + wn2 - 2.0f * a1.x, 0.0f));
            dv.w = sqrtf(fmaxf(xr + wn3 - 2.0f * a1.y, 0.0f));
            *(float4*)&g_dist[row * M_N + c0 + tx * 4] = dv;
        }
    } else {
        // proto tile: accumulate sum over tile of edge_prob(i,j) * d2(i,j)
        float pdsum = 0.0f;
        #pragma unroll
        for (int r = 0; r < 4; ++r) {
            int i = r0 + ty * 4 + r;
            float xr = s_xn[ty * 4 + r];
            float2 a0 = unpack2(acc[r][0]), a1 = unpack2(acc[r][1]);
            float d2[4];
            d2[0] = fmaxf(xr + wn0 - 2.0f * a0.x, 0.0f);
            d2[1] = fmaxf(xr + wn1 - 2.0f * a0.y, 0.0f);
            d2[2] = fmaxf(xr + wn2 - 2.0f * a1.x, 0.0f);
            d2[3] = fmaxf(xr + wn3 - 2.0f * a1.y, 0.0f);
            float4 eij = *(const float4*)&E[i * M_N + c0 + tx * 4];
            #pragma unroll
            for (int q = 0; q < 4; ++q) {
                int j = c0 + tx * 4 + q;
                float e2 = E[j * M_N + i];
                float e1 = (q == 0) ? eij.x : (q == 1) ? eij.y : (q == 2) ? eij.z : eij.w;
                float z = 0.5f * (e1 + e2);
                float pp = (i != j) ? 1.0f / (1.0f + __expf(-z)) : 0.0f;
                pdsum = fmaf(pp, d2[q], pdsum);
            }
        }
        __syncthreads();                    // xs reuse as reduction buffer
        float s = block_reduce_256(pdsum, xs);
        if (tid == 0) g_pdpart[pb] = s;
    }
}

// ---------------- off-diagonal tile pair with antisymmetric reuse ------
__device__ __forceinline__ void tilepair(const unsigned* dup, unsigned di2, int lane,
                                         int J, int slot, float& sx, float& sy,
                                         float2* part) {
    const unsigned* tj = dup + J * 64;
    float sjx = 0.0f, sjy = 0.0f;
    #pragma unroll
    for (int kg = 0; kg < 8; ++kg) {
        unsigned sacc = 0u, racc = 0u;
        #pragma unroll
        for (int q = 0; q < 4; ++q) {
            const int k = kg * 4 + q;
            unsigned dj = tj[lane ^ k];
            unsigned t  = h2tanh(h2sub(di2, dj));
            unsigned r  = __shfl_xor_sync(FULLM, t, k);
            sacc = h2add(sacc, t);
            racc = h2add(racc, r);
        }
        h2acc(sacc, sx, sy);        // si += sum t
        h2accneg(racc, sjx, sjy);   // sj -= sum r
    }
    part[(J * 4 + slot) * 32 + lane] = make_float2(sjx, sjy);
}

// ---------------- rank: halved f16x2 tanh + fused final ----------------
__global__ __launch_bounds__(256) void k_rank2(float* __restrict__ out) {
    __shared__ __align__(16) unsigned dup[8 * 64];
    __shared__ float2 part[8 * 4 * 32];
    __shared__ float redx[256];
    __shared__ float redy[256];
    __shared__ bool amLast;

    const int tid  = threadIdx.x;
    const int lane = tid & 31;
    const int w    = tid >> 5;
    const int p    = blockIdx.x;

    float d0  = g_dist[(2 * p + 0) * M_N + tid];
    float d1  = g_dist[(2 * p + 1) * M_N + tid];
    float fac = g_factor[tid];

    // exact fp32 row means (for fp16 centering)
    redx[tid] = d0; redy[tid] = d1;
    __syncthreads();
    #pragma unroll
    for (int s = 128; s > 0; s >>= 1) {
        if (tid < s) { redx[tid] += redx[tid + s]; redy[tid] += redy[tid + s]; }
        __syncthreads();
    }
    float m0 = redx[0] * (1.0f / 256.0f);
    float m1 = redy[0] * (1.0f / 256.0f);
    __syncthreads();

    __half2 hc = __floats2half2_rn((d0 - m0) * INV2TAU_F, (d1 - m1) * INV2TAU_F);
    unsigned hcu = *reinterpret_cast<unsigned*>(&hc);
    dup[w * 64 + lane]      = hcu;
    dup[w * 64 + 32 + lane] = hcu;
    __syncthreads();

    const unsigned di2 = dup[w * 64 + lane];
    float sx = 0.0f, sy = 0.0f;

    // ---- diagonal tile: rotation k=1..15 with reuse, k=16 unhalved ----
    {
        const unsigned* tw = dup + w * 64;
        unsigned sacc = 0u, racc = 0u;
        #pragma unroll
        for (int k = 1; k <= 15; ++k) {
            unsigned dj = tw[lane + k];
            unsigned t  = h2tanh(h2sub(di2, dj));
            unsigned r  = __shfl_sync(FULLM, t, (lane - k) & 31);
            sacc = h2add(sacc, t);
            racc = h2add(racc, r);
            if ((k & 3) == 0 || k == 15) {
                h2acc(sacc, sx, sy);
                h2accneg(racc, sx, sy);
                sacc = 0u; racc = 0u;
            }
        }
        unsigned dj = tw[lane + 16];
        unsigned t  = h2tanh(h2sub(di2, dj));
        h2acc(t, sx, sy);
    }

    // ---- off-diagonal tile pairs (each unordered pair once) ----
    tilepair(dup, di2, lane, (w + 1) & 7, 0, sx, sy, part);
    tilepair(dup, di2, lane, (w + 2) & 7, 1, sx, sy, part);
    tilepair(dup, di2, lane, (w + 3) & 7, 2, sx, sy, part);
    if (w < 4) tilepair(dup, di2, lane, w + 4, 3, sx, sy, part);
    __syncthreads();

    {
        float2 q0 = part[(w * 4 + 0) * 32 + lane];
        float2 q1 = part[(w * 4 + 1) * 32 + lane];
        float2 q2 = part[(w * 4 + 2) * 32 + lane];
        sx += q0.x + q1.x + q2.x;
        sy += q0.y + q1.y + q2.y;
        if (w >= 4) {
            float2 q3 = part[(w * 4 + 3) * 32 + lane];
            sx += q3.x; sy += q3.y;
        }
    }

    float srm0 = 127.5f + 0.5f * sx;
    float srm1 = 127.5f + 0.5f * sy;
    float contrib = exp2f(srm0 * NEIGH_LOG2) * fac * d0
                  + exp2f(srm1 * NEIGH_LOG2) * fac * d1;

    float s = block_reduce_256(contrib, redx);
    if (tid == 0) g_partial[p] = s;

    // ---- last block computes the final scalar ----
    if (tid == 0) {
        __threadfence();
        amLast = (atomicAdd(&g_ctr, 1) == NPAIR - 1);
    }
    __syncthreads();
    if (amLast) {
        float acc = 0.0f;
        #pragma unroll
        for (int i = tid; i < NPAIR; i += 256) acc += g_partial[i];
        float data_sum = block_reduce_256(acc, redx);
        float sp  = block_reduce_256(g_rowp[tid], redx);
        float pdv = (tid < 16) ? g_pdpart[tid] : 0.0f;
        float spd = block_reduce_256(pdv, redx);
        if (tid == 0) {
            float data_term = data_sum / ((float)B_N * (float)M_N);
            float wlen      = spd / (sp + 1e-8f);
            float sparsity  = sp / ((float)M_N * (float)M_N);
            out[0] = data_term + LEN_C_F * wlen + SP_C_F * sparsity;
        }
    }
}

// ---------------- launch ----------------
extern "C" void kernel_launch(void* const* d_in, const int* in_sizes, int n_in,
                              void* d_out, int out_size) {
    const float* data = (const float*)d_in[0];   // [4096, 256]
    const float* w    = (const float*)d_in[1];   // [256, 256]
    const float* E    = (const float*)d_in[2];   // [256, 256]
    float* out = (float*)d_out;

    k_pre   <<<M_N, 256>>>(E, w);       // rowp/factor/wsq + ctr reset
    k_gemm  <<<272, 256>>>(data, w, E); // dists + proto pd partials
    k_rank2 <<<NPAIR, 256>>>(out);
}

// round 16
// speedup vs baseline: 1.0099x; 1.0099x over previous
#include <cuda_runtime.h>
#include <cuda_fp16.h>
#include <math.h>

// Problem constants
#define B_N   4096
#define M_N   256
#define D_N   256
#define TAU_F       0.2f
#define INV2TAU_F   2.5f
#define TOPO_F      0.5f
#define LEN_C_F     0.01f
#define SP_C_F      0.001f
#define NEIGH_LOG2  (-0.18033688011112042f)   // -log2(e)/8
#define NPAIR (B_N / 2)                       // 2048 row pairs
#define FULLM 0xffffffffu

// ---------------- device scratch ----------------
__device__ float g_dist[B_N * M_N];
__device__ float g_factor[M_N];
__device__ float g_wsq[M_N];
__device__ float g_rowp[M_N];
__device__ float g_pdpart[8];                // per-proto-block sum edge_prob * d2
__device__ float g_partial[NPAIR];
__device__ int   g_ctr;                      // rank last-block counter (reset by L1)
__device__ int   g_flag;                     // factor-blocks-done flag (reset by L2)

// ---------------- helpers ----------------
__device__ __forceinline__ unsigned h2tanh(unsigned x) {
    unsigned y;
    asm("tanh.approx.f16x2 %0, %1;" : "=r"(y) : "r"(x));
    return y;
}
__device__ __forceinline__ unsigned h2sub(unsigned a, unsigned b) {
    unsigned r;
    asm("sub.f16x2 %0, %1, %2;" : "=r"(r) : "r"(a), "r"(b));
    return r;
}
__device__ __forceinline__ unsigned h2add(unsigned a, unsigned b) {
    unsigned r;
    asm("add.f16x2 %0, %1, %2;" : "=r"(r) : "r"(a), "r"(b));
    return r;
}
__device__ __forceinline__ void h2acc(unsigned h2, float& a, float& b) {
    __half2 h = *reinterpret_cast<__half2*>(&h2);
    float2 f = __half22float2(h);
    a += f.x; b += f.y;
}
__device__ __forceinline__ void h2accneg(unsigned h2, float& a, float& b) {
    __half2 h = *reinterpret_cast<__half2*>(&h2);
    float2 f = __half22float2(h);
    a -= f.x; b -= f.y;
}

// packed f32x2 FMA (sm_103a)
__device__ __forceinline__ unsigned long long ffma2(unsigned long long a,
                                                    unsigned long long b,
                                                    unsigned long long c) {
    unsigned long long d;
    asm("fma.rn.f32x2 %0, %1, %2, %3;" : "=l"(d) : "l"(a), "l"(b), "l"(c));
    return d;
}
__device__ __forceinline__ unsigned long long pack2(float x) {
    unsigned long long r;
    asm("mov.b64 %0, {%1, %1};" : "=l"(r) : "f"(x));
    return r;
}
__device__ __forceinline__ float2 unpack2(unsigned long long v) {
    float2 f;
    asm("mov.b64 {%0, %1}, %2;" : "=f"(f.x), "=f"(f.y) : "l"(v));
    return f;
}

__device__ __forceinline__ float warp_reduce(float p) {
    #pragma unroll
    for (int off = 16; off > 0; off >>= 1) p += __shfl_xor_sync(FULLM, p, off);
    return p;
}

__device__ __forceinline__ float block_reduce_256(float v, float* sh) {
    int t = threadIdx.x;
    sh[t] = v;
    __syncthreads();
    #pragma unroll
    for (int s = 128; s > 0; s >>= 1) {
        if (t < s) sh[t] += sh[t + s];
        __syncthreads();
    }
    float r = sh[0];
    __syncthreads();
    return r;
}

// ============ L1: fused gemm + edge/factor/norm preprocessing ============
// grid 144, 256 threads:
//   blocks 0..7    : factor blocks -> g_wsq, g_rowp, g_factor, then g_flag++
//   blocks 8..15   : proto tiles (32 W-rows x 256 protos) -> g_pdpart
//   blocks 16..143 : data tiles  (32 rows x 256 protos)   -> g_dist
__global__ __launch_bounds__(256) void k_gemm(const float* __restrict__ A,
                                              const float* __restrict__ W,
                                              const float* __restrict__ E) {
    __shared__ __align__(16) float xs[32 * 256];        // 32 KB [row][k]
    __shared__ __align__(16) float ws[2][16 * 260];     // 33.3 KB [buf][kc][proto pad]
    __shared__ float s_xn[32];

    const int tid  = threadIdx.x;
    const int lane = tid & 31;
    const int w8   = tid >> 5;          // warp 0..7
    const int bid  = blockIdx.x;

    // ---------------- factor blocks ----------------
    if (bid < 8) {
        if (bid == 0 && tid == 0) g_ctr = 0;     // reset rank counter each replay
        const int i0 = bid * 32;
        #pragma unroll
        for (int rr = 0; rr < 4; ++rr) {
            int i = i0 + w8 * 4 + rr;
            // W row norm
            const float4* Wr = (const float4*)(W + i * D_N);
            float4 a = Wr[lane], c = Wr[lane + 32];
            float p = a.x*a.x + a.y*a.y + a.z*a.z + a.w*a.w
                    + c.x*c.x + c.y*c.y + c.z*c.z + c.w*c.w;
            p = warp_reduce(p);
            if (lane == 0) g_wsq[i] = p;
            // edge row sum
            float q = 0.0f;
            #pragma unroll
            for (int it = 0; it < 8; ++it) {
                int j = it * 32 + lane;
                float z = 0.5f * (E[i * M_N + j] + E[j * M_N + i]);
                if (j != i) q += 1.0f / (1.0f + __expf(-z));
            }
            q = warp_reduce(q);
            if (lane == 0) {
                g_rowp[i]   = q;
                g_factor[i] = 1.0f + TOPO_F * q / (float)(M_N - 1);
            }
        }
        __threadfence();
        __syncthreads();
        if (tid == 0) atomicAdd(&g_flag, 1);
        return;
    }

    // ---------------- gemm blocks ----------------
    const bool proto = (bid < 16);
    const int r0 = proto ? (bid - 8) * 32 : (bid - 16) * 32;
    const float* Ain = proto ? W : A;
    const int tx = tid & 31;            // proto groups {tx*4, 128+tx*4}
    const int ty = tid >> 5;            // rows ty*4 .. ty*4+3

    // ---- load A tile [32][256] (coalesced float4) ----
    #pragma unroll
    for (int it = 0; it < 8; ++it) {
        int fidx = it * 256 + tid;           // float4 index 0..2047
        int row = fidx >> 6, k4 = fidx & 63;
        float4 v = ((const float4*)(Ain + (r0 + row) * D_N))[k4];
        *(float4*)&xs[row * 256 + k4 * 4] = v;
    }
    __syncthreads();

    // ---- row norms of the tile: warp w8 -> rows w8*4 .. +3 ----
    #pragma unroll
    for (int rr = 0; rr < 4; ++rr) {
        int row = w8 * 4 + rr;
        const float4* xr4 = (const float4*)&xs[row * 256];
        float4 a = xr4[lane], b = xr4[lane + 32];
        float p = a.x*a.x + a.y*a.y + a.z*a.z + a.w*a.w
                + b.x*b.x + b.y*b.y + b.z*b.z + b.w*b.w;
        p = warp_reduce(p);
        if (lane == 0) s_xn[row] = p;
    }

    // ---- stage chunk 0: ws[0][dc][proto] ----
    #pragma unroll
    for (int it = 0; it < 4; ++it) {
        int fidx = it * 256 + tid;           // 0..1023
        int mm = fidx >> 2, dc4 = fidx & 3;
        float4 v = *(const float4*)&W[mm * 256 + dc4 * 4];
        ws[0][(dc4 * 4 + 0) * 260 + mm] = v.x;
        ws[0][(dc4 * 4 + 1) * 260 + mm] = v.y;
        ws[0][(dc4 * 4 + 2) * 260 + mm] = v.z;
        ws[0][(dc4 * 4 + 3) * 260 + mm] = v.w;
    }
    __syncthreads();

    unsigned long long acc[4][4];
    #pragma unroll
    for (int r = 0; r < 4; ++r)
        #pragma unroll
        for (int q = 0; q < 4; ++q) acc[r][q] = 0ull;

    #pragma unroll 1
    for (int c = 0; c < 16; ++c) {
        const int b = c & 1;
        // prefetch next chunk into registers (LDG latency hidden by compute)
        float4 pre[4];
        if (c < 15) {
            #pragma unroll
            for (int it = 0; it < 4; ++it) {
                int fidx = it * 256 + tid;
                int mm = fidx >> 2, dc4 = fidx & 3;
                pre[it] = *(const float4*)&W[mm * 256 + (c + 1) * 16 + dc4 * 4];
            }
        }

        // compute chunk c from ws[b]
        const float* wsb = ws[b];
        #pragma unroll
        for (int kq = 0; kq < 4; ++kq) {
            float4 xr[4];
            #pragma unroll
            for (int r = 0; r < 4; ++r)
                xr[r] = *(const float4*)&xs[(ty * 4 + r) * 256 + c * 16 + kq * 4];
            #pragma unroll
            for (int k2 = 0; k2 < 4; ++k2) {
                const int kc = kq * 4 + k2;
                ulonglong2 wA = *(const ulonglong2*)&wsb[kc * 260 + tx * 4];
                ulonglong2 wB = *(const ulonglong2*)&wsb[kc * 260 + 128 + tx * 4];
                #pragma unroll
                for (int r = 0; r < 4; ++r) {
                    float xv = (k2 == 0) ? xr[r].x : (k2 == 1) ? xr[r].y
                             : (k2 == 2) ? xr[r].z : xr[r].w;
                    unsigned long long xx = pack2(xv);
                    acc[r][0] = ffma2(xx, wA.x, acc[r][0]);
                    acc[r][1] = ffma2(xx, wA.y, acc[r][1]);
                    acc[r][2] = ffma2(xx, wB.x, acc[r][2]);
                    acc[r][3] = ffma2(xx, wB.y, acc[r][3]);
                }
            }
        }

        // stage next chunk into the other buffer
        if (c < 15) {
            float* wsn = ws[1 - b];
            #pragma unroll
            for (int it = 0; it < 4; ++it) {
                int fidx = it * 256 + tid;
                int mm = fidx >> 2, dc4 = fidx & 3;
                wsn[(dc4 * 4 + 0) * 260 + mm] = pre[it].x;
                wsn[(dc4 * 4 + 1) * 260 + mm] = pre[it].y;
                wsn[(dc4 * 4 + 2) * 260 + mm] = pre[it].z;
                wsn[(dc4 * 4 + 3) * 260 + mm] = pre[it].w;
            }
            __syncthreads();
        }
    }

    // ---- wait for factor blocks (expected: already done) ----
    if (tid == 0) {
        while (*((volatile int*)&g_flag) < 8) __nanosleep(64);
    }
    __syncthreads();

    float4 wnA = __ldcg((const float4*)&g_wsq[tx * 4]);
    float4 wnB = __ldcg((const float4*)&g_wsq[128 + tx * 4]);

    if (!proto) {
        #pragma unroll
        for (int r = 0; r < 4; ++r) {
            int row = r0 + ty * 4 + r;
            float xr = s_xn[ty * 4 + r];
            float2 a0 = unpack2(acc[r][0]), a1 = unpack2(acc[r][1]);
            float2 a2 = unpack2(acc[r][2]), a3 = unpack2(acc[r][3]);
            float4 dA, dB;
            dA.x = sqrtf(fmaxf(xr + wnA.x - 2.0f * a0.x, 0.0f));
            dA.y = sqrtf(fmaxf(xr + wnA.y - 2.0f * a0.y, 0.0f));
            dA.z = sqrtf(fmaxf(xr + wnA.z - 2.0f * a1.x, 0.0f));
            dA.w = sqrtf(fmaxf(xr + wnA.w - 2.0f * a1.y, 0.0f));
            dB.x = sqrtf(fmaxf(xr + wnB.x - 2.0f * a2.x, 0.0f));
            dB.y = sqrtf(fmaxf(xr + wnB.y - 2.0f * a2.y, 0.0f));
            dB.z = sqrtf(fmaxf(xr + wnB.z - 2.0f * a3.x, 0.0f));
            dB.w = sqrtf(fmaxf(xr + wnB.w - 2.0f * a3.y, 0.0f));
            *(float4*)&g_dist[row * M_N + tx * 4]       = dA;
            *(float4*)&g_dist[row * M_N + 128 + tx * 4] = dB;
        }
    } else {
        // proto tile: accumulate sum over tile of edge_prob(i,j) * d2(i,j)
        float pdsum = 0.0f;
        #pragma unroll
        for (int r = 0; r < 4; ++r) {
            int i = r0 + ty * 4 + r;
            float xr = s_xn[ty * 4 + r];
            float2 a0 = unpack2(acc[r][0]), a1 = unpack2(acc[r][1]);
            float2 a2 = unpack2(acc[r][2]), a3 = unpack2(acc[r][3]);
            float d2[8];
            d2[0] = fmaxf(xr + wnA.x - 2.0f * a0.x, 0.0f);
            d2[1] = fmaxf(xr + wnA.y - 2.0f * a0.y, 0.0f);
            d2[2] = fmaxf(xr + wnA.z - 2.0f * a1.x, 0.0f);
            d2[3] = fmaxf(xr + wnA.w - 2.0f * a1.y, 0.0f);
            d2[4] = fmaxf(xr + wnB.x - 2.0f * a2.x, 0.0f);
            d2[5] = fmaxf(xr + wnB.y - 2.0f * a2.y, 0.0f);
            d2[6] = fmaxf(xr + wnB.z - 2.0f * a3.x, 0.0f);
            d2[7] = fmaxf(xr + wnB.w - 2.0f * a3.y, 0.0f);
            float4 eA = *(const float4*)&E[i * M_N + tx * 4];
            float4 eB = *(const float4*)&E[i * M_N + 128 + tx * 4];
            #pragma unroll
            for (int q = 0; q < 8; ++q) {
                int j = (q < 4) ? (tx * 4 + q) : (128 + tx * 4 + q - 4);
                float e1 = (q == 0) ? eA.x : (q == 1) ? eA.y : (q == 2) ? eA.z
                         : (q == 3) ? eA.w : (q == 4) ? eB.x : (q == 5) ? eB.y
                         : (q == 6) ? eB.z : eB.w;
                float e2 = E[j * M_N + i];
                float z = 0.5f * (e1 + e2);
                float pp = (i != j) ? 1.0f / (1.0f + __expf(-z)) : 0.0f;
                pdsum = fmaf(pp, d2[q], pdsum);
            }
        }
        __syncthreads();                    // xs reuse as reduction buffer
        float s = block_reduce_256(pdsum, xs);
        if (tid == 0) g_pdpart[bid - 8] = s;
    }
}

// ---------------- off-diagonal tile pair with antisymmetric reuse ------
__device__ __forceinline__ void tilepair(const unsigned* dup, unsigned di2, int lane,
                                         int J, int slot, float& sx, float& sy,
                                         float2* part) {
    const unsigned* tj = dup + J * 64;
    float sjx = 0.0f, sjy = 0.0f;
    #pragma unroll
    for (int kg = 0; kg < 8; ++kg) {
        unsigned sacc = 0u, racc = 0u;
        #pragma unroll
        for (int q = 0; q < 4; ++q) {
            const int k = kg * 4 + q;
            unsigned dj = tj[lane ^ k];
            unsigned t  = h2tanh(h2sub(di2, dj));
            unsigned r  = __shfl_xor_sync(FULLM, t, k);
            sacc = h2add(sacc, t);
            racc = h2add(racc, r);
        }
        h2acc(sacc, sx, sy);        // si += sum t
        h2accneg(racc, sjx, sjy);   // sj -= sum r
    }
    part[(J * 4 + slot) * 32 + lane] = make_float2(sjx, sjy);
}

// ============ L2: rank (halved f16x2 tanh) + fused final ============
__global__ __launch_bounds__(256) void k_rank2(float* __restrict__ out) {
    __shared__ __align__(16) unsigned dup[8 * 64];
    __shared__ float2 part[8 * 4 * 32];
    __shared__ float redx[256];
    __shared__ float redy[256];
    __shared__ bool amLast;

    const int tid  = threadIdx.x;
    const int lane = tid & 31;
    const int w    = tid >> 5;
    const int p    = blockIdx.x;

    float d0  = g_dist[(2 * p + 0) * M_N + tid];
    float d1  = g_dist[(2 * p + 1) * M_N + tid];
    float fac = g_factor[tid];

    // exact fp32 row means (for fp16 centering)
    redx[tid] = d0; redy[tid] = d1;
    __syncthreads();
    #pragma unroll
    for (int s = 128; s > 0; s >>= 1) {
        if (tid < s) { redx[tid] += redx[tid + s]; redy[tid] += redy[tid + s]; }
        __syncthreads();
    }
    float m0 = redx[0] * (1.0f / 256.0f);
    float m1 = redy[0] * (1.0f / 256.0f);
    __syncthreads();

    __half2 hc = __floats2half2_rn((d0 - m0) * INV2TAU_F, (d1 - m1) * INV2TAU_F);
    unsigned hcu = *reinterpret_cast<unsigned*>(&hc);
    dup[w * 64 + lane]      = hcu;
    dup[w * 64 + 32 + lane] = hcu;
    __syncthreads();

    const unsigned di2 = dup[w * 64 + lane];
    float sx = 0.0f, sy = 0.0f;

    // ---- diagonal tile: rotation k=1..15 with reuse, k=16 unhalved ----
    {
        const unsigned* tw = dup + w * 64;
        unsigned sacc = 0u, racc = 0u;
        #pragma unroll
        for (int k = 1; k <= 15; ++k) {
            unsigned dj = tw[lane + k];
            unsigned t  = h2tanh(h2sub(di2, dj));
            unsigned r  = __shfl_sync(FULLM, t, (lane - k) & 31);
            sacc = h2add(sacc, t);
            racc = h2add(racc, r);
            if ((k & 3) == 0 || k == 15) {
                h2acc(sacc, sx, sy);
                h2accneg(racc, sx, sy);
                sacc = 0u; racc = 0u;
            }
        }
        unsigned dj = tw[lane + 16];
        unsigned t  = h2tanh(h2sub(di2, dj));
        h2acc(t, sx, sy);
    }

    // ---- off-diagonal tile pairs (each unordered pair once) ----
    tilepair(dup, di2, lane, (w + 1) & 7, 0, sx, sy, part);
    tilepair(dup, di2, lane, (w + 2) & 7, 1, sx, sy, part);
    tilepair(dup, di2, lane, (w + 3) & 7, 2, sx, sy, part);
    if (w < 4) tilepair(dup, di2, lane, w + 4, 3, sx, sy, part);
    __syncthreads();

    {
        float2 q0 = part[(w * 4 + 0) * 32 + lane];
        float2 q1 = part[(w * 4 + 1) * 32 + lane];
        float2 q2 = part[(w * 4 + 2) * 32 + lane];
        sx += q0.x + q1.x + q2.x;
        sy += q0.y + q1.y + q2.y;
        if (w >= 4) {
            float2 q3 = part[(w * 4 + 3) * 32 + lane];
            sx += q3.x; sy += q3.y;
        }
    }

    float srm0 = 127.5f + 0.5f * sx;
    float srm1 = 127.5f + 0.5f * sy;
    float contrib = exp2f(srm0 * NEIGH_LOG2) * fac * d0
                  + exp2f(srm1 * NEIGH_LOG2) * fac * d1;

    float s = block_reduce_256(contrib, redx);
    if (tid == 0) g_partial[p] = s;

    // ---- last block computes the final scalar ----
    if (tid == 0) {
        __threadfence();
        amLast = (atomicAdd(&g_ctr, 1) == NPAIR - 1);
    }
    __syncthreads();
    if (amLast) {
        float acc = 0.0f;
        #pragma unroll
        for (int i = tid; i < NPAIR; i += 256) acc += g_partial[i];
        float data_sum = block_reduce_256(acc, redx);
        float sp  = block_reduce_256(g_rowp[tid], redx);
        float pdv = (tid < 8) ? g_pdpart[tid] : 0.0f;
        float spd = block_reduce_256(pdv, redx);
        if (tid == 0) {
            float data_term = data_sum / ((float)B_N * (float)M_N);
            float wlen      = spd / (sp + 1e-8f);
            float sparsity  = sp / ((float)M_N * (float)M_N);
            out[0] = data_term + LEN_C_F * wlen + SP_C_F * sparsity;
            g_flag = 0;                      // re-arm for next graph replay
        }
    }
}

// ---------------- launch ----------------
extern "C" void kernel_launch(void* const* d_in, const int* in_sizes, int n_in,
                              void* d_out, int out_size) {
    const float* data = (const float*)d_in[0];   // [4096, 256]
    const float* w    = (const float*)d_in[1];   // [256, 256]
    const float* E    = (const float*)d_in[2];   // [256, 256]
    float* out = (float*)d_out;

    k_gemm  <<<144, 256>>>(data, w, E);   // factor + proto-pd + data dists
    k_rank2 <<<NPAIR, 256>>>(out);
}